// round 14
// baseline (speedup 1.0000x reference)
#include <cuda_runtime.h>
#include <cuda_fp16.h>
#include <math.h>
#include <cstdint>

// Problem constants
#define BATCH 2
#define SEQ 2048
#define DMODEL 1024
#define NHEADS 16
#define HDIM 64
#define BH (BATCH*NHEADS)          // 32
#define MROWS (BATCH*SEQ)          // 4096

// fp16 scratch (static device arrays -- no allocation allowed)
__device__ __half g_xh[MROWS * DMODEL];
__device__ __half g_Wqh[DMODEL * DMODEL];
__device__ __half g_Wkh[DMODEL * DMODEL];
__device__ __half g_Wvh[DMODEL * DMODEL];
__device__ __half g_Woh[DMODEL * DMODEL];
__device__ __half g_Qh[BH * SEQ * HDIM];   // roped + scaled
__device__ __half g_Kh[BH * SEQ * HDIM];   // roped
__device__ __half g_Vh[BH * SEQ * HDIM];
__device__ __half g_Ch[MROWS * DMODEL];    // context [B,S,D]

// ===========================================================================
// Helpers
// ===========================================================================
__device__ __forceinline__ void mma_f16(float& d0, float& d1, float& d2, float& d3,
                                        uint32_t a0, uint32_t a1, uint32_t a2, uint32_t a3,
                                        uint32_t b0, uint32_t b1) {
    asm volatile(
        "mma.sync.aligned.m16n8k16.row.col.f32.f16.f16.f32 "
        "{%0,%1,%2,%3}, {%4,%5,%6,%7}, {%8,%9}, {%0,%1,%2,%3};"
        : "+f"(d0), "+f"(d1), "+f"(d2), "+f"(d3)
        : "r"(a0), "r"(a1), "r"(a2), "r"(a3), "r"(b0), "r"(b1));
}

__device__ __forceinline__ void ldmatrix_x4(uint32_t& r0, uint32_t& r1,
                                            uint32_t& r2, uint32_t& r3,
                                            uint32_t addr) {
    asm volatile("ldmatrix.sync.aligned.m8n8.x4.shared.b16 {%0,%1,%2,%3}, [%4];"
                 : "=r"(r0), "=r"(r1), "=r"(r2), "=r"(r3) : "r"(addr));
}

__device__ __forceinline__ void ldmatrix_x2_trans(uint32_t& r0, uint32_t& r1,
                                                  uint32_t addr) {
    asm volatile("ldmatrix.sync.aligned.m8n8.x2.trans.shared.b16 {%0,%1}, [%2];"
                 : "=r"(r0), "=r"(r1) : "r"(addr));
}

__device__ __forceinline__ void cp_async16(uint32_t smem_addr, const void* gmem) {
    asm volatile("cp.async.cg.shared.global [%0], [%1], 16;"
                 :: "r"(smem_addr), "l"(gmem) : "memory");
}
#define CP_ASYNC_COMMIT() asm volatile("cp.async.commit_group;" ::: "memory")
#define CP_ASYNC_WAIT(n)  asm volatile("cp.async.wait_group %0;" :: "n"(n) : "memory")

__device__ __forceinline__ uint32_t smem_u32(const void* p) {
    uint32_t a;
    asm("{ .reg .u64 t; cvta.to.shared.u64 t, %1; cvt.u32.u64 %0, t; }"
        : "=r"(a) : "l"(p));
    return a;
}

__device__ __forceinline__ uint32_t h2u(__half2 h) {
    return *(uint32_t*)&h;
}

// ---------------------------------------------------------------------------
// Fused fp32 -> fp16 conversion: each thread converts 8 float4 (128B, MLP 8)
// ---------------------------------------------------------------------------
#define XN4 (MROWS * DMODEL / 4)      // 1048576
#define WN4 (DMODEL * DMODEL / 4)     // 262144
#define TOT4 (XN4 + 4 * WN4)          // 2097152
#define CVT_THREADS (TOT4 / 8)        // 262144

__global__ __launch_bounds__(256) void cvt_all(
    const float* __restrict__ x,
    const float* __restrict__ wq, const float* __restrict__ wk,
    const float* __restrict__ wv, const float* __restrict__ wo,
    __half* __restrict__ xh,
    __half* __restrict__ wqh, __half* __restrict__ wkh,
    __half* __restrict__ wvh, __half* __restrict__ woh)
{
    int i = blockIdx.x * blockDim.x + threadIdx.x;
    if (i >= CVT_THREADS) return;
    int e0 = i * 8;   // first float4 index; group of 8 never crosses a tensor
    const float* src;
    __half* dst;
    int off;
    if (e0 < XN4) {
        src = x; dst = xh; off = e0;
    } else {
        int j = e0 - XN4;
        int w = j >> 18;
        off = j & (WN4 - 1);
        src = (w == 0) ? wq : (w == 1) ? wk : (w == 2) ? wv : wo;
        dst = (w == 0) ? wqh : (w == 1) ? wkh : (w == 2) ? wvh : woh;
    }
    float4 v[8];
#pragma unroll
    for (int u = 0; u < 8; u++)
        v[u] = *(const float4*)&src[(size_t)(off + u) * 4];
#pragma unroll
    for (int u = 0; u < 8; u++) {
        *(__half2*)&dst[(size_t)(off + u) * 4] = __floats2half2_rn(v[u].x, v[u].y);
        *(__half2*)&dst[(size_t)(off + u) * 4 + 2] = __floats2half2_rn(v[u].z, v[u].w);
    }
}

// ===========================================================================
// fp16 mma GEMM (round-8 config): CTA 128x64, 8 warps 4Mx2N, warp tile 32x32,
// BK=32, 4-stage cp.async ring, 3 CTAs/SM.
// ===========================================================================
#define TBM 128
#define TBN 64
#define TBK 32
#define NCH (DMODEL / TBK)        // 32
#define HSTR 40                   // halves per smem row (80B)
#define STAGE_ROWS (TBM + TBN)    // 192
#define STAGE_H (STAGE_ROWS * HSTR)
#define GSTAGES 4
#define GSM_BYTES (GSTAGES * STAGE_H * 2)   // 61440 B

__global__ __launch_bounds__(256, 3)
void gemm_h(const __half* __restrict__ A,
            const __half* __restrict__ W0, const __half* __restrict__ W1,
            const __half* __restrict__ W2,
            const float* __restrict__ b0p, const float* __restrict__ b1p,
            const float* __restrict__ b2p,
            float* __restrict__ outf,
            __half* __restrict__ o0, __half* __restrict__ o1,
            __half* __restrict__ o2,
            int fused)
{
    extern __shared__ __align__(16) __half smh[];
    const uint32_t sb = smem_u32(smh);

    const int z = fused ? blockIdx.z : 0;
    const int mode = fused ? (z + 1) : 0;
    const __half* W = (z == 0) ? W0 : (z == 1) ? W1 : W2;
    const float* bias = (z == 0) ? b0p : (z == 1) ? b1p : b2p;
    __half* outh = (z == 0) ? o0 : (z == 1) ? o1 : o2;

    const int tid = threadIdx.x;
    const int wid = tid >> 5;
    const int lane = tid & 31;
    const int wm = wid & 3;
    const int wn = wid >> 2;
    const int g = lane >> 2;
    const int t = lane & 3;

    const int row0 = blockIdx.y * TBM;
    const int col0 = blockIdx.x * TBN;

    const int r0l = tid >> 2;
    const int off_h = (tid & 3) * 8;
    const uint32_t ls0 = (uint32_t)(r0l * HSTR + off_h) * 2;
    const uint32_t ls1 = (uint32_t)((r0l + 64) * HSTR + off_h) * 2;
    const uint32_t ls2 = (uint32_t)((r0l + 128) * HSTR + off_h) * 2;
    const __half* g0 = &A[(size_t)(row0 + r0l) * DMODEL + off_h];
    const __half* g1 = &A[(size_t)(row0 + r0l + 64) * DMODEL + off_h];
    const __half* g2 = &W[(size_t)(col0 + r0l) * DMODEL + off_h];

    const int lr8 = lane & 7;
    const int lg8 = (lane >> 3) & 1;
    const int lk8 = (lane >> 4) & 1;

    float acc[2][4][4];
#pragma unroll
    for (int i = 0; i < 2; i++)
#pragma unroll
        for (int j = 0; j < 4; j++)
#pragma unroll
            for (int r = 0; r < 4; r++) acc[i][j][r] = 0.f;

#pragma unroll
    for (int p = 0; p < GSTAGES - 1; p++) {
        uint32_t stb = sb + (uint32_t)(p * STAGE_H) * 2;
        const int k0 = p * TBK;
        cp_async16(stb + ls0, g0 + k0);
        cp_async16(stb + ls1, g1 + k0);
        cp_async16(stb + ls2, g2 + k0);
        CP_ASYNC_COMMIT();
    }

    for (int c = 0; c < NCH; c++) {
        CP_ASYNC_WAIT(GSTAGES - 2);
        __syncthreads();

        if (c + GSTAGES - 1 < NCH) {
            const int st = (c + GSTAGES - 1) & (GSTAGES - 1);
            uint32_t stb = sb + (uint32_t)(st * STAGE_H) * 2;
            const int k0 = (c + GSTAGES - 1) * TBK;
            cp_async16(stb + ls0, g0 + k0);
            cp_async16(stb + ls1, g1 + k0);
            cp_async16(stb + ls2, g2 + k0);
        }
        CP_ASYNC_COMMIT();

        const uint32_t stb = sb + (uint32_t)((c & (GSTAGES - 1)) * STAGE_H) * 2;
#pragma unroll
        for (int ks = 0; ks < 2; ks++) {
            const uint32_t acol = (uint32_t)(ks * 16 + lk8 * 8) * 2;
            uint32_t afr[2][4];
#pragma unroll
            for (int am = 0; am < 2; am++) {
                int r = wm * 32 + am * 16 + lr8 + lg8 * 8;
                ldmatrix_x4(afr[am][0], afr[am][1], afr[am][2], afr[am][3],
                            stb + (uint32_t)(r * HSTR) * 2 + acol);
            }
            uint32_t bfr[4][2];
#pragma unroll
            for (int bnp = 0; bnp < 2; bnp++) {
                int n = wn * 32 + bnp * 16 + lr8 + lg8 * 8;
                ldmatrix_x4(bfr[2 * bnp][0], bfr[2 * bnp + 1][0],
                            bfr[2 * bnp][1], bfr[2 * bnp + 1][1],
                            stb + (uint32_t)((128 + n) * HSTR) * 2 + acol);
            }
#pragma unroll
            for (int am = 0; am < 2; am++)
#pragma unroll
                for (int bn = 0; bn < 4; bn++)
                    mma_f16(acc[am][bn][0], acc[am][bn][1],
                            acc[am][bn][2], acc[am][bn][3],
                            afr[am][0], afr[am][1], afr[am][2], afr[am][3],
                            bfr[bn][0], bfr[bn][1]);
        }
    }

    // ---- epilogue ----
#pragma unroll
    for (int bn = 0; bn < 4; bn++) {
        const int n0 = col0 + wn * 32 + bn * 8 + 2 * t;
        const float b0 = __ldg(&bias[n0]);
        const float b1 = __ldg(&bias[n0 + 1]);

        float invf = 0.f;
        if (mode == 1 || mode == 2) {
            int pair = (n0 & 63) >> 1;
            invf = powf(10000.0f, -(float)pair / 32.0f);
        }
#pragma unroll
        for (int am = 0; am < 2; am++) {
            const int r0 = row0 + wm * 32 + am * 16 + g;
#pragma unroll
            for (int rh = 0; rh < 2; rh++) {
                const int r = r0 + rh * 8;
                float v0 = acc[am][bn][rh * 2] + b0;
                float v1 = acc[am][bn][rh * 2 + 1] + b1;
                if (mode == 0) {
                    *(float2*)&outf[(size_t)r * DMODEL + n0] = make_float2(v0, v1);
                } else {
                    const int b = r >> 11;
                    const int s = r & (SEQ - 1);
                    const int h = n0 >> 6;
                    const int d = n0 & 63;
                    if (mode != 3) {
                        float sn, cs;
                        sincosf((float)s * invf, &sn, &cs);
                        float oe = v0 * cs - v1 * sn;
                        float oo = v0 * sn + v1 * cs;
                        if (mode == 1) { oe *= 0.125f; oo *= 0.125f; }
                        v0 = oe; v1 = oo;
                    }
                    __half2 hv = __floats2half2_rn(v0, v1);
                    *(__half2*)&outh[(((size_t)(b * NHEADS + h)) * SEQ + s) * HDIM + d] = hv;
                }
            }
        }
    }
}

// ===========================================================================
// fp16 flash attention (round-12 config): 3-stage KV ring, one barrier per
// 64-col k-tile, kk=0 V-fragment preload. CTA = (bh, 128-row q tile), 8 warps.
// ===========================================================================
#define KVSTR 72
#define KV_TILE_H (64 * KVSTR)
#define ASTAGES 3
#define AT_SMEM_BYTES (ASTAGES * 2 * KV_TILE_H * 2)   // 55296 B

__global__ __launch_bounds__(256)
void attn_h(const __half* __restrict__ Q,
            const __half* __restrict__ K,
            const __half* __restrict__ V,
            __half* __restrict__ C)
{
    extern __shared__ __align__(16) __half smh[];
    const uint32_t sb = smem_u32(smh);

    const int bh = blockIdx.y;
    const int qt = gridDim.x - 1 - blockIdx.x;   // heavy tiles first
    const int q0 = qt * 128;
    const int tid = threadIdx.x;
    const int wid = tid >> 5;
    const int lane = tid & 31;
    const int g = lane >> 2;
    const int t = lane & 3;
    const int rb = wid * 16;

    const int lr8 = lane & 7;
    const int lg8 = (lane >> 3) & 1;
    const int lk8 = (lane >> 4) & 1;

    const __half* Qb = Q + (((size_t)bh * SEQ) + q0) * HDIM;
    const __half* Kh = K + ((size_t)bh * SEQ) * HDIM;
    const __half* Vh = V + ((size_t)bh * SEQ) * HDIM;

    // Q fragments straight from gmem (pre-roped, pre-scaled)
    uint32_t qfr[4][4];
#pragma unroll
    for (int ks = 0; ks < 4; ks++) {
        const int d0 = ks * 16;
        qfr[ks][0] = *(const uint32_t*)&Qb[(rb + g) * HDIM + d0 + 2 * t];
        qfr[ks][1] = *(const uint32_t*)&Qb[(rb + g + 8) * HDIM + d0 + 2 * t];
        qfr[ks][2] = *(const uint32_t*)&Qb[(rb + g) * HDIM + d0 + 2 * t + 8];
        qfr[ks][3] = *(const uint32_t*)&Qb[(rb + g + 8) * HDIM + d0 + 2 * t + 8];
    }

    float oa[8][4];
#pragma unroll
    for (int a = 0; a < 8; a++)
#pragma unroll
        for (int r = 0; r < 4; r++) oa[a][r] = 0.f;
    float m_i[2] = {-INFINITY, -INFINITY};
    float l_i[2] = {0.f, 0.f};

    const int nkt = (q0 + 128) >> 6;

    const int lrow = tid >> 2;
    const int lhf = (tid & 3) * 16;
    const uint32_t lsoff = (uint32_t)(lrow * KVSTR + lhf) * 2;

    // prologue: tiles 0 and 1 (nkt >= 2 always)
#pragma unroll
    for (int p = 0; p < ASTAGES - 1; p++) {
        uint32_t kb = sb + (uint32_t)(p * 2 * KV_TILE_H) * 2;
        uint32_t vb = kb + (uint32_t)KV_TILE_H * 2;
        const size_t r = (size_t)(p * 64 + lrow) * HDIM + lhf;
        cp_async16(kb + lsoff, &Kh[r]);
        cp_async16(kb + lsoff + 16, &Kh[r + 8]);
        cp_async16(vb + lsoff, &Vh[r]);
        cp_async16(vb + lsoff + 16, &Vh[r + 8]);
        CP_ASYNC_COMMIT();
    }

    int stc = 0;
    for (int kt = 0; kt < nkt; kt++) {
        CP_ASYNC_WAIT(ASTAGES - 2);
        __syncthreads();

        if (kt + ASTAGES - 1 < nkt) {
            int stn = stc + (ASTAGES - 1);
            if (stn >= ASTAGES) stn -= ASTAGES;
            uint32_t kb = sb + (uint32_t)(stn * 2 * KV_TILE_H) * 2;
            uint32_t vb = kb + (uint32_t)KV_TILE_H * 2;
            const size_t r = (size_t)((kt + ASTAGES - 1) * 64 + lrow) * HDIM + lhf;
            cp_async16(kb + lsoff, &Kh[r]);
            cp_async16(kb + lsoff + 16, &Kh[r + 8]);
            cp_async16(vb + lsoff, &Vh[r]);
            cp_async16(vb + lsoff + 16, &Vh[r + 8]);
        }
        CP_ASYNC_COMMIT();

        const uint32_t ksb = sb + (uint32_t)(stc * 2 * KV_TILE_H) * 2;
        const uint32_t vsb = ksb + (uint32_t)KV_TILE_H * 2;
        const int k0g = kt * 64;
        if (++stc == ASTAGES) stc = 0;

        // ---- S = Q K^T ----
        float sa[8][4];
#pragma unroll
        for (int a = 0; a < 8; a++)
#pragma unroll
            for (int r = 0; r < 4; r++) sa[a][r] = 0.f;

#pragma unroll
        for (int ks = 0; ks < 4; ks++) {
            const uint32_t kcol = (uint32_t)(ks * 16 + lk8 * 8) * 2;
            uint32_t bk[8][2];
#pragma unroll
            for (int ap = 0; ap < 4; ap++) {
                int n = ap * 16 + lr8 + lg8 * 8;
                ldmatrix_x4(bk[2 * ap][0], bk[2 * ap + 1][0],
                            bk[2 * ap][1], bk[2 * ap + 1][1],
                            ksb + (uint32_t)(n * KVSTR) * 2 + kcol);
            }
#pragma unroll
            for (int a = 0; a < 8; a++)
                mma_f16(sa[a][0], sa[a][1], sa[a][2], sa[a][3],
                        qfr[ks][0], qfr[ks][1], qfr[ks][2], qfr[ks][3],
                        bk[a][0], bk[a][1]);
        }

        // ---- preload kk=0 V fragments (overlaps LDSM latency with softmax) ----
        uint32_t v0fr[8][2];
        {
            const uint32_t rowaddr0 = vsb + (uint32_t)((lane & 15) * KVSTR) * 2;
#pragma unroll
            for (int a = 0; a < 8; a++)
                ldmatrix_x2_trans(v0fr[a][0], v0fr[a][1], rowaddr0 + a * 16);
        }

        // ---- causal mask ----
        if (k0g + 63 > q0 + rb) {
            const int r0g = q0 + rb + g;
            const int r1g = r0g + 8;
#pragma unroll
            for (int a = 0; a < 8; a++) {
                int c0 = k0g + a * 8 + 2 * t;
                int c1 = c0 + 1;
                if (c0 > r0g) sa[a][0] = -INFINITY;
                if (c1 > r0g) sa[a][1] = -INFINITY;
                if (c0 > r1g) sa[a][2] = -INFINITY;
                if (c1 > r1g) sa[a][3] = -INFINITY;
            }
        }

        // ---- online softmax ----
#pragma unroll
        for (int rh = 0; rh < 2; rh++) {
            const int s0 = rh * 2;
            float mt = -INFINITY;
#pragma unroll
            for (int a = 0; a < 8; a++)
                mt = fmaxf(mt, fmaxf(sa[a][s0], sa[a][s0 + 1]));
            mt = fmaxf(mt, __shfl_xor_sync(0xffffffffu, mt, 1));
            mt = fmaxf(mt, __shfl_xor_sync(0xffffffffu, mt, 2));
            float mn = fmaxf(m_i[rh], mt);
            float corr = __expf(m_i[rh] - mn);
            float lt = 0.f;
#pragma unroll
            for (int a = 0; a < 8; a++) {
                sa[a][s0] = __expf(sa[a][s0] - mn);
                sa[a][s0 + 1] = __expf(sa[a][s0 + 1] - mn);
                lt += sa[a][s0] + sa[a][s0 + 1];
            }
            lt += __shfl_xor_sync(0xffffffffu, lt, 1);
            lt += __shfl_xor_sync(0xffffffffu, lt, 2);
            l_i[rh] = l_i[rh] * corr + lt;
            m_i[rh] = mn;
#pragma unroll
            for (int a = 0; a < 8; a++) {
                oa[a][s0] *= corr;
                oa[a][s0 + 1] *= corr;
            }
        }

        // ---- O += P V ----
#pragma unroll
        for (int kk = 0; kk < 4; kk++) {
            uint32_t pa0 = h2u(__floats2half2_rn(sa[2 * kk][0], sa[2 * kk][1]));
            uint32_t pa1 = h2u(__floats2half2_rn(sa[2 * kk][2], sa[2 * kk][3]));
            uint32_t pa2 = h2u(__floats2half2_rn(sa[2 * kk + 1][0], sa[2 * kk + 1][1]));
            uint32_t pa3 = h2u(__floats2half2_rn(sa[2 * kk + 1][2], sa[2 * kk + 1][3]));
            if (kk == 0) {
#pragma unroll
                for (int a = 0; a < 8; a++)
                    mma_f16(oa[a][0], oa[a][1], oa[a][2], oa[a][3],
                            pa0, pa1, pa2, pa3, v0fr[a][0], v0fr[a][1]);
            } else {
                const uint32_t rowaddr = vsb +
                    (uint32_t)((kk * 16 + (lane & 15)) * KVSTR) * 2;
#pragma unroll
                for (int a = 0; a < 8; a++) {
                    uint32_t b0, b1;
                    ldmatrix_x2_trans(b0, b1, rowaddr + a * 16);
                    mma_f16(oa[a][0], oa[a][1], oa[a][2], oa[a][3],
                            pa0, pa1, pa2, pa3, b0, b1);
                }
            }
        }
    }

    // ---- write context fp16 [B,S,D] ----
    const int b = bh >> 4;
    const int h = bh & 15;
    const float inv0 = 1.0f / l_i[0];
    const float inv1 = 1.0f / l_i[1];
    const int row0 = q0 + rb + g;
    const int row1 = row0 + 8;
#pragma unroll
    for (int a = 0; a < 8; a++) {
        int d = h * HDIM + a * 8 + 2 * t;
        *(__half2*)&C[((size_t)b * SEQ + row0) * DMODEL + d] =
            __floats2half2_rn(oa[a][0] * inv0, oa[a][1] * inv0);
        *(__half2*)&C[((size_t)b * SEQ + row1) * DMODEL + d] =
            __floats2half2_rn(oa[a][2] * inv1, oa[a][3] * inv1);
    }
}

// ---------------------------------------------------------------------------
// Launch
// ---------------------------------------------------------------------------
extern "C" void kernel_launch(void* const* d_in, const int* in_sizes, int n_in,
                              void* d_out, int out_size)
{
    const float* x  = (const float*)d_in[0];
    const float* Wq = (const float*)d_in[1];
    const float* bq = (const float*)d_in[2];
    const float* Wk = (const float*)d_in[3];
    const float* bk = (const float*)d_in[4];
    const float* Wv = (const float*)d_in[5];
    const float* bv = (const float*)d_in[6];
    const float* Wo = (const float*)d_in[7];
    const float* bo = (const float*)d_in[8];
    float* out = (float*)d_out;

    __half *xh, *Wqh, *Wkh, *Wvh, *Woh, *Qh, *Kh, *Vh, *Ch;
    cudaGetSymbolAddress((void**)&xh, g_xh);
    cudaGetSymbolAddress((void**)&Wqh, g_Wqh);
    cudaGetSymbolAddress((void**)&Wkh, g_Wkh);
    cudaGetSymbolAddress((void**)&Wvh, g_Wvh);
    cudaGetSymbolAddress((void**)&Woh, g_Woh);
    cudaGetSymbolAddress((void**)&Qh, g_Qh);
    cudaGetSymbolAddress((void**)&Kh, g_Kh);
    cudaGetSymbolAddress((void**)&Vh, g_Vh);
    cudaGetSymbolAddress((void**)&Ch, g_Ch);

    static int attr_set = 0;
    if (!attr_set) {
        cudaFuncSetAttribute(attn_h,
                             cudaFuncAttributeMaxDynamicSharedMemorySize,
                             AT_SMEM_BYTES);
        cudaFuncSetAttribute(gemm_h,
                             cudaFuncAttributeMaxDynamicSharedMemorySize,
                             GSM_BYTES);
        attr_set = 1;
    }

    cvt_all<<<(CVT_THREADS + 255) / 256, 256>>>(x, Wq, Wk, Wv, Wo,
                                                xh, Wqh, Wkh, Wvh, Woh);

    dim3 gq(DMODEL / TBN, MROWS / TBM, 3);  // (16, 32, 3) fused QKV
    gemm_h<<<gq, 256, GSM_BYTES>>>(xh, Wqh, Wkh, Wvh, bq, bk, bv,
                                   nullptr, Qh, Kh, Vh, 1);

    dim3 agrid(SEQ / 128, BH);
    attn_h<<<agrid, 256, AT_SMEM_BYTES>>>(Qh, Kh, Vh, Ch);

    dim3 go(DMODEL / TBN, MROWS / TBM, 1);  // (16, 32)
    gemm_h<<<go, 256, GSM_BYTES>>>(Ch, Woh, nullptr, nullptr, bo, nullptr, nullptr,
                                   out, nullptr, nullptr, nullptr, 0);
}

// round 15
// speedup vs baseline: 1.0150x; 1.0150x over previous
#include <cuda_runtime.h>
#include <cuda_fp16.h>
#include <math.h>
#include <cstdint>

// Problem constants
#define BATCH 2
#define SEQ 2048
#define DMODEL 1024
#define NHEADS 16
#define HDIM 64
#define BH (BATCH*NHEADS)          // 32
#define MROWS (BATCH*SEQ)          // 4096

// fp16 scratch (static device arrays -- no allocation allowed)
__device__ __half g_xh[MROWS * DMODEL];
__device__ __half g_Wqh[DMODEL * DMODEL];
__device__ __half g_Wkh[DMODEL * DMODEL];
__device__ __half g_Wvh[DMODEL * DMODEL];
__device__ __half g_Woh[DMODEL * DMODEL];
__device__ __half g_Qh[BH * SEQ * HDIM];   // roped + scaled
__device__ __half g_Kh[BH * SEQ * HDIM];   // roped
__device__ __half g_Vh[BH * SEQ * HDIM];
__device__ __half g_Ch[MROWS * DMODEL];    // context [B,S,D]

// ===========================================================================
// Helpers
// ===========================================================================
__device__ __forceinline__ void mma_f16(float& d0, float& d1, float& d2, float& d3,
                                        uint32_t a0, uint32_t a1, uint32_t a2, uint32_t a3,
                                        uint32_t b0, uint32_t b1) {
    asm volatile(
        "mma.sync.aligned.m16n8k16.row.col.f32.f16.f16.f32 "
        "{%0,%1,%2,%3}, {%4,%5,%6,%7}, {%8,%9}, {%0,%1,%2,%3};"
        : "+f"(d0), "+f"(d1), "+f"(d2), "+f"(d3)
        : "r"(a0), "r"(a1), "r"(a2), "r"(a3), "r"(b0), "r"(b1));
}

__device__ __forceinline__ void ldmatrix_x4(uint32_t& r0, uint32_t& r1,
                                            uint32_t& r2, uint32_t& r3,
                                            uint32_t addr) {
    asm volatile("ldmatrix.sync.aligned.m8n8.x4.shared.b16 {%0,%1,%2,%3}, [%4];"
                 : "=r"(r0), "=r"(r1), "=r"(r2), "=r"(r3) : "r"(addr));
}

__device__ __forceinline__ void ldmatrix_x2_trans(uint32_t& r0, uint32_t& r1,
                                                  uint32_t addr) {
    asm volatile("ldmatrix.sync.aligned.m8n8.x2.trans.shared.b16 {%0,%1}, [%2];"
                 : "=r"(r0), "=r"(r1) : "r"(addr));
}

__device__ __forceinline__ void cp_async16(uint32_t smem_addr, const void* gmem) {
    asm volatile("cp.async.cg.shared.global [%0], [%1], 16;"
                 :: "r"(smem_addr), "l"(gmem) : "memory");
}
#define CP_ASYNC_COMMIT() asm volatile("cp.async.commit_group;" ::: "memory")
#define CP_ASYNC_WAIT(n)  asm volatile("cp.async.wait_group %0;" :: "n"(n) : "memory")

__device__ __forceinline__ uint32_t smem_u32(const void* p) {
    uint32_t a;
    asm("{ .reg .u64 t; cvta.to.shared.u64 t, %1; cvt.u32.u64 %0, t; }"
        : "=r"(a) : "l"(p));
    return a;
}

__device__ __forceinline__ uint32_t h2u(__half2 h) {
    return *(uint32_t*)&h;
}

// ---------------------------------------------------------------------------
// Fused fp32 -> fp16 conversion: each thread converts 4 float4 (64B)
// ---------------------------------------------------------------------------
#define XN4 (MROWS * DMODEL / 4)      // 1048576
#define WN4 (DMODEL * DMODEL / 4)     // 262144
#define TOT4 (XN4 + 4 * WN4)          // 2097152
#define CVT_THREADS (TOT4 / 4)        // 524288

__global__ __launch_bounds__(256) void cvt_all(
    const float* __restrict__ x,
    const float* __restrict__ wq, const float* __restrict__ wk,
    const float* __restrict__ wv, const float* __restrict__ wo,
    __half* __restrict__ xh,
    __half* __restrict__ wqh, __half* __restrict__ wkh,
    __half* __restrict__ wvh, __half* __restrict__ woh)
{
    int i = blockIdx.x * blockDim.x + threadIdx.x;
    if (i >= CVT_THREADS) return;
    int e0 = i * 4;
    const float* src;
    __half* dst;
    int off;
    if (e0 < XN4) {
        src = x; dst = xh; off = e0;
    } else {
        int j = e0 - XN4;
        int w = j >> 18;
        off = j & (WN4 - 1);
        src = (w == 0) ? wq : (w == 1) ? wk : (w == 2) ? wv : wo;
        dst = (w == 0) ? wqh : (w == 1) ? wkh : (w == 2) ? wvh : woh;
    }
#pragma unroll
    for (int u = 0; u < 4; u++) {
        float4 v = *(const float4*)&src[(size_t)(off + u) * 4];
        *(__half2*)&dst[(size_t)(off + u) * 4] = __floats2half2_rn(v.x, v.y);
        *(__half2*)&dst[(size_t)(off + u) * 4 + 2] = __floats2half2_rn(v.z, v.w);
    }
}

// ===========================================================================
// fp16 mma GEMM (round-8 config): CTA 128x64, 8 warps 4Mx2N, warp tile 32x32,
// BK=32, 4-stage cp.async ring, 3 CTAs/SM.
// ===========================================================================
#define TBM 128
#define TBN 64
#define TBK 32
#define NCH (DMODEL / TBK)        // 32
#define HSTR 40                   // halves per smem row (80B)
#define STAGE_ROWS (TBM + TBN)    // 192
#define STAGE_H (STAGE_ROWS * HSTR)
#define GSTAGES 4
#define GSM_BYTES (GSTAGES * STAGE_H * 2)   // 61440 B

__global__ __launch_bounds__(256, 3)
void gemm_h(const __half* __restrict__ A,
            const __half* __restrict__ W0, const __half* __restrict__ W1,
            const __half* __restrict__ W2,
            const float* __restrict__ b0p, const float* __restrict__ b1p,
            const float* __restrict__ b2p,
            float* __restrict__ outf,
            __half* __restrict__ o0, __half* __restrict__ o1,
            __half* __restrict__ o2,
            int fused)
{
    extern __shared__ __align__(16) __half smh[];
    const uint32_t sb = smem_u32(smh);

    const int z = fused ? blockIdx.z : 0;
    const int mode = fused ? (z + 1) : 0;
    const __half* W = (z == 0) ? W0 : (z == 1) ? W1 : W2;
    const float* bias = (z == 0) ? b0p : (z == 1) ? b1p : b2p;
    __half* outh = (z == 0) ? o0 : (z == 1) ? o1 : o2;

    const int tid = threadIdx.x;
    const int wid = tid >> 5;
    const int lane = tid & 31;
    const int wm = wid & 3;
    const int wn = wid >> 2;
    const int g = lane >> 2;
    const int t = lane & 3;

    const int row0 = blockIdx.y * TBM;
    const int col0 = blockIdx.x * TBN;

    const int r0l = tid >> 2;
    const int off_h = (tid & 3) * 8;
    const uint32_t ls0 = (uint32_t)(r0l * HSTR + off_h) * 2;
    const uint32_t ls1 = (uint32_t)((r0l + 64) * HSTR + off_h) * 2;
    const uint32_t ls2 = (uint32_t)((r0l + 128) * HSTR + off_h) * 2;
    const __half* g0 = &A[(size_t)(row0 + r0l) * DMODEL + off_h];
    const __half* g1 = &A[(size_t)(row0 + r0l + 64) * DMODEL + off_h];
    const __half* g2 = &W[(size_t)(col0 + r0l) * DMODEL + off_h];

    const int lr8 = lane & 7;
    const int lg8 = (lane >> 3) & 1;
    const int lk8 = (lane >> 4) & 1;

    float acc[2][4][4];
#pragma unroll
    for (int i = 0; i < 2; i++)
#pragma unroll
        for (int j = 0; j < 4; j++)
#pragma unroll
            for (int r = 0; r < 4; r++) acc[i][j][r] = 0.f;

#pragma unroll
    for (int p = 0; p < GSTAGES - 1; p++) {
        uint32_t stb = sb + (uint32_t)(p * STAGE_H) * 2;
        const int k0 = p * TBK;
        cp_async16(stb + ls0, g0 + k0);
        cp_async16(stb + ls1, g1 + k0);
        cp_async16(stb + ls2, g2 + k0);
        CP_ASYNC_COMMIT();
    }

    for (int c = 0; c < NCH; c++) {
        CP_ASYNC_WAIT(GSTAGES - 2);
        __syncthreads();

        if (c + GSTAGES - 1 < NCH) {
            const int st = (c + GSTAGES - 1) & (GSTAGES - 1);
            uint32_t stb = sb + (uint32_t)(st * STAGE_H) * 2;
            const int k0 = (c + GSTAGES - 1) * TBK;
            cp_async16(stb + ls0, g0 + k0);
            cp_async16(stb + ls1, g1 + k0);
            cp_async16(stb + ls2, g2 + k0);
        }
        CP_ASYNC_COMMIT();

        const uint32_t stb = sb + (uint32_t)((c & (GSTAGES - 1)) * STAGE_H) * 2;
#pragma unroll
        for (int ks = 0; ks < 2; ks++) {
            const uint32_t acol = (uint32_t)(ks * 16 + lk8 * 8) * 2;
            uint32_t afr[2][4];
#pragma unroll
            for (int am = 0; am < 2; am++) {
                int r = wm * 32 + am * 16 + lr8 + lg8 * 8;
                ldmatrix_x4(afr[am][0], afr[am][1], afr[am][2], afr[am][3],
                            stb + (uint32_t)(r * HSTR) * 2 + acol);
            }
            uint32_t bfr[4][2];
#pragma unroll
            for (int bnp = 0; bnp < 2; bnp++) {
                int n = wn * 32 + bnp * 16 + lr8 + lg8 * 8;
                ldmatrix_x4(bfr[2 * bnp][0], bfr[2 * bnp + 1][0],
                            bfr[2 * bnp][1], bfr[2 * bnp + 1][1],
                            stb + (uint32_t)((128 + n) * HSTR) * 2 + acol);
            }
#pragma unroll
            for (int am = 0; am < 2; am++)
#pragma unroll
                for (int bn = 0; bn < 4; bn++)
                    mma_f16(acc[am][bn][0], acc[am][bn][1],
                            acc[am][bn][2], acc[am][bn][3],
                            afr[am][0], afr[am][1], afr[am][2], afr[am][3],
                            bfr[bn][0], bfr[bn][1]);
        }
    }

    // ---- epilogue ----
#pragma unroll
    for (int bn = 0; bn < 4; bn++) {
        const int n0 = col0 + wn * 32 + bn * 8 + 2 * t;
        const float b0 = __ldg(&bias[n0]);
        const float b1 = __ldg(&bias[n0 + 1]);

        float invf = 0.f;
        if (mode == 1 || mode == 2) {
            int pair = (n0 & 63) >> 1;
            invf = powf(10000.0f, -(float)pair / 32.0f);
        }
#pragma unroll
        for (int am = 0; am < 2; am++) {
            const int r0 = row0 + wm * 32 + am * 16 + g;
#pragma unroll
            for (int rh = 0; rh < 2; rh++) {
                const int r = r0 + rh * 8;
                float v0 = acc[am][bn][rh * 2] + b0;
                float v1 = acc[am][bn][rh * 2 + 1] + b1;
                if (mode == 0) {
                    *(float2*)&outf[(size_t)r * DMODEL + n0] = make_float2(v0, v1);
                } else {
                    const int b = r >> 11;
                    const int s = r & (SEQ - 1);
                    const int h = n0 >> 6;
                    const int d = n0 & 63;
                    if (mode != 3) {
                        float sn, cs;
                        sincosf((float)s * invf, &sn, &cs);
                        float oe = v0 * cs - v1 * sn;
                        float oo = v0 * sn + v1 * cs;
                        if (mode == 1) { oe *= 0.125f; oo *= 0.125f; }
                        v0 = oe; v1 = oo;
                    }
                    __half2 hv = __floats2half2_rn(v0, v1);
                    *(__half2*)&outh[(((size_t)(b * NHEADS + h)) * SEQ + s) * HDIM + d] = hv;
                }
            }
        }
    }
}

// ===========================================================================
// fp16 flash attention (round-12 config): 3-stage KV ring, one barrier per
// 64-col k-tile, kk=0 V-fragment preload. CTA = (bh, 128-row q tile), 8 warps.
// ===========================================================================
#define KVSTR 72
#define KV_TILE_H (64 * KVSTR)
#define ASTAGES 3
#define AT_SMEM_BYTES (ASTAGES * 2 * KV_TILE_H * 2)   // 55296 B

__global__ __launch_bounds__(256)
void attn_h(const __half* __restrict__ Q,
            const __half* __restrict__ K,
            const __half* __restrict__ V,
            __half* __restrict__ C)
{
    extern __shared__ __align__(16) __half smh[];
    const uint32_t sb = smem_u32(smh);

    const int bh = blockIdx.y;
    const int qt = gridDim.x - 1 - blockIdx.x;   // heavy tiles first
    const int q0 = qt * 128;
    const int tid = threadIdx.x;
    const int wid = tid >> 5;
    const int lane = tid & 31;
    const int g = lane >> 2;
    const int t = lane & 3;
    const int rb = wid * 16;

    const int lr8 = lane & 7;
    const int lg8 = (lane >> 3) & 1;
    const int lk8 = (lane >> 4) & 1;

    const __half* Qb = Q + (((size_t)bh * SEQ) + q0) * HDIM;
    const __half* Kh = K + ((size_t)bh * SEQ) * HDIM;
    const __half* Vh = V + ((size_t)bh * SEQ) * HDIM;

    // Q fragments straight from gmem (pre-roped, pre-scaled)
    uint32_t qfr[4][4];
#pragma unroll
    for (int ks = 0; ks < 4; ks++) {
        const int d0 = ks * 16;
        qfr[ks][0] = *(const uint32_t*)&Qb[(rb + g) * HDIM + d0 + 2 * t];
        qfr[ks][1] = *(const uint32_t*)&Qb[(rb + g + 8) * HDIM + d0 + 2 * t];
        qfr[ks][2] = *(const uint32_t*)&Qb[(rb + g) * HDIM + d0 + 2 * t + 8];
        qfr[ks][3] = *(const uint32_t*)&Qb[(rb + g + 8) * HDIM + d0 + 2 * t + 8];
    }

    float oa[8][4];
#pragma unroll
    for (int a = 0; a < 8; a++)
#pragma unroll
        for (int r = 0; r < 4; r++) oa[a][r] = 0.f;
    float m_i[2] = {-INFINITY, -INFINITY};
    float l_i[2] = {0.f, 0.f};

    const int nkt = (q0 + 128) >> 6;

    const int lrow = tid >> 2;
    const int lhf = (tid & 3) * 16;
    const uint32_t lsoff = (uint32_t)(lrow * KVSTR + lhf) * 2;

    // prologue: tiles 0 and 1 (nkt >= 2 always)
#pragma unroll
    for (int p = 0; p < ASTAGES - 1; p++) {
        uint32_t kb = sb + (uint32_t)(p * 2 * KV_TILE_H) * 2;
        uint32_t vb = kb + (uint32_t)KV_TILE_H * 2;
        const size_t r = (size_t)(p * 64 + lrow) * HDIM + lhf;
        cp_async16(kb + lsoff, &Kh[r]);
        cp_async16(kb + lsoff + 16, &Kh[r + 8]);
        cp_async16(vb + lsoff, &Vh[r]);
        cp_async16(vb + lsoff + 16, &Vh[r + 8]);
        CP_ASYNC_COMMIT();
    }

    int stc = 0;
    for (int kt = 0; kt < nkt; kt++) {
        CP_ASYNC_WAIT(ASTAGES - 2);
        __syncthreads();

        if (kt + ASTAGES - 1 < nkt) {
            int stn = stc + (ASTAGES - 1);
            if (stn >= ASTAGES) stn -= ASTAGES;
            uint32_t kb = sb + (uint32_t)(stn * 2 * KV_TILE_H) * 2;
            uint32_t vb = kb + (uint32_t)KV_TILE_H * 2;
            const size_t r = (size_t)((kt + ASTAGES - 1) * 64 + lrow) * HDIM + lhf;
            cp_async16(kb + lsoff, &Kh[r]);
            cp_async16(kb + lsoff + 16, &Kh[r + 8]);
            cp_async16(vb + lsoff, &Vh[r]);
            cp_async16(vb + lsoff + 16, &Vh[r + 8]);
        }
        CP_ASYNC_COMMIT();

        const uint32_t ksb = sb + (uint32_t)(stc * 2 * KV_TILE_H) * 2;
        const uint32_t vsb = ksb + (uint32_t)KV_TILE_H * 2;
        const int k0g = kt * 64;
        if (++stc == ASTAGES) stc = 0;

        // ---- S = Q K^T ----
        float sa[8][4];
#pragma unroll
        for (int a = 0; a < 8; a++)
#pragma unroll
            for (int r = 0; r < 4; r++) sa[a][r] = 0.f;

#pragma unroll
        for (int ks = 0; ks < 4; ks++) {
            const uint32_t kcol = (uint32_t)(ks * 16 + lk8 * 8) * 2;
            uint32_t bk[8][2];
#pragma unroll
            for (int ap = 0; ap < 4; ap++) {
                int n = ap * 16 + lr8 + lg8 * 8;
                ldmatrix_x4(bk[2 * ap][0], bk[2 * ap + 1][0],
                            bk[2 * ap][1], bk[2 * ap + 1][1],
                            ksb + (uint32_t)(n * KVSTR) * 2 + kcol);
            }
#pragma unroll
            for (int a = 0; a < 8; a++)
                mma_f16(sa[a][0], sa[a][1], sa[a][2], sa[a][3],
                        qfr[ks][0], qfr[ks][1], qfr[ks][2], qfr[ks][3],
                        bk[a][0], bk[a][1]);
        }

        // ---- preload kk=0 V fragments (overlaps LDSM latency with softmax) ----
        uint32_t v0fr[8][2];
        {
            const uint32_t rowaddr0 = vsb + (uint32_t)((lane & 15) * KVSTR) * 2;
#pragma unroll
            for (int a = 0; a < 8; a++)
                ldmatrix_x2_trans(v0fr[a][0], v0fr[a][1], rowaddr0 + a * 16);
        }

        // ---- causal mask ----
        if (k0g + 63 > q0 + rb) {
            const int r0g = q0 + rb + g;
            const int r1g = r0g + 8;
#pragma unroll
            for (int a = 0; a < 8; a++) {
                int c0 = k0g + a * 8 + 2 * t;
                int c1 = c0 + 1;
                if (c0 > r0g) sa[a][0] = -INFINITY;
                if (c1 > r0g) sa[a][1] = -INFINITY;
                if (c0 > r1g) sa[a][2] = -INFINITY;
                if (c1 > r1g) sa[a][3] = -INFINITY;
            }
        }

        // ---- online softmax ----
#pragma unroll
        for (int rh = 0; rh < 2; rh++) {
            const int s0 = rh * 2;
            float mt = -INFINITY;
#pragma unroll
            for (int a = 0; a < 8; a++)
                mt = fmaxf(mt, fmaxf(sa[a][s0], sa[a][s0 + 1]));
            mt = fmaxf(mt, __shfl_xor_sync(0xffffffffu, mt, 1));
            mt = fmaxf(mt, __shfl_xor_sync(0xffffffffu, mt, 2));
            float mn = fmaxf(m_i[rh], mt);
            float corr = __expf(m_i[rh] - mn);
            float lt = 0.f;
#pragma unroll
            for (int a = 0; a < 8; a++) {
                sa[a][s0] = __expf(sa[a][s0] - mn);
                sa[a][s0 + 1] = __expf(sa[a][s0 + 1] - mn);
                lt += sa[a][s0] + sa[a][s0 + 1];
            }
            lt += __shfl_xor_sync(0xffffffffu, lt, 1);
            lt += __shfl_xor_sync(0xffffffffu, lt, 2);
            l_i[rh] = l_i[rh] * corr + lt;
            m_i[rh] = mn;
#pragma unroll
            for (int a = 0; a < 8; a++) {
                oa[a][s0] *= corr;
                oa[a][s0 + 1] *= corr;
            }
        }

        // ---- O += P V ----
#pragma unroll
        for (int kk = 0; kk < 4; kk++) {
            uint32_t pa0 = h2u(__floats2half2_rn(sa[2 * kk][0], sa[2 * kk][1]));
            uint32_t pa1 = h2u(__floats2half2_rn(sa[2 * kk][2], sa[2 * kk][3]));
            uint32_t pa2 = h2u(__floats2half2_rn(sa[2 * kk + 1][0], sa[2 * kk + 1][1]));
            uint32_t pa3 = h2u(__floats2half2_rn(sa[2 * kk + 1][2], sa[2 * kk + 1][3]));
            if (kk == 0) {
#pragma unroll
                for (int a = 0; a < 8; a++)
                    mma_f16(oa[a][0], oa[a][1], oa[a][2], oa[a][3],
                            pa0, pa1, pa2, pa3, v0fr[a][0], v0fr[a][1]);
            } else {
                const uint32_t rowaddr = vsb +
                    (uint32_t)((kk * 16 + (lane & 15)) * KVSTR) * 2;
#pragma unroll
                for (int a = 0; a < 8; a++) {
                    uint32_t b0, b1;
                    ldmatrix_x2_trans(b0, b1, rowaddr + a * 16);
                    mma_f16(oa[a][0], oa[a][1], oa[a][2], oa[a][3],
                            pa0, pa1, pa2, pa3, b0, b1);
                }
            }
        }
    }

    // ---- write context fp16 [B,S,D] ----
    const int b = bh >> 4;
    const int h = bh & 15;
    const float inv0 = 1.0f / l_i[0];
    const float inv1 = 1.0f / l_i[1];
    const int row0 = q0 + rb + g;
    const int row1 = row0 + 8;
#pragma unroll
    for (int a = 0; a < 8; a++) {
        int d = h * HDIM + a * 8 + 2 * t;
        *(__half2*)&C[((size_t)b * SEQ + row0) * DMODEL + d] =
            __floats2half2_rn(oa[a][0] * inv0, oa[a][1] * inv0);
        *(__half2*)&C[((size_t)b * SEQ + row1) * DMODEL + d] =
            __floats2half2_rn(oa[a][2] * inv1, oa[a][3] * inv1);
    }
}

// ---------------------------------------------------------------------------
// Launch
// ---------------------------------------------------------------------------
extern "C" void kernel_launch(void* const* d_in, const int* in_sizes, int n_in,
                              void* d_out, int out_size)
{
    const float* x  = (const float*)d_in[0];
    const float* Wq = (const float*)d_in[1];
    const float* bq = (const float*)d_in[2];
    const float* Wk = (const float*)d_in[3];
    const float* bk = (const float*)d_in[4];
    const float* Wv = (const float*)d_in[5];
    const float* bv = (const float*)d_in[6];
    const float* Wo = (const float*)d_in[7];
    const float* bo = (const float*)d_in[8];
    float* out = (float*)d_out;

    __half *xh, *Wqh, *Wkh, *Wvh, *Woh, *Qh, *Kh, *Vh, *Ch;
    cudaGetSymbolAddress((void**)&xh, g_xh);
    cudaGetSymbolAddress((void**)&Wqh, g_Wqh);
    cudaGetSymbolAddress((void**)&Wkh, g_Wkh);
    cudaGetSymbolAddress((void**)&Wvh, g_Wvh);
    cudaGetSymbolAddress((void**)&Woh, g_Woh);
    cudaGetSymbolAddress((void**)&Qh, g_Qh);
    cudaGetSymbolAddress((void**)&Kh, g_Kh);
    cudaGetSymbolAddress((void**)&Vh, g_Vh);
    cudaGetSymbolAddress((void**)&Ch, g_Ch);

    static int attr_set = 0;
    if (!attr_set) {
        cudaFuncSetAttribute(attn_h,
                             cudaFuncAttributeMaxDynamicSharedMemorySize,
                             AT_SMEM_BYTES);
        cudaFuncSetAttribute(gemm_h,
                             cudaFuncAttributeMaxDynamicSharedMemorySize,
                             GSM_BYTES);
        attr_set = 1;
    }

    cvt_all<<<(CVT_THREADS + 255) / 256, 256>>>(x, Wq, Wk, Wv, Wo,
                                                xh, Wqh, Wkh, Wvh, Woh);

    dim3 gq(DMODEL / TBN, MROWS / TBM, 3);  // (16, 32, 3) fused QKV
    gemm_h<<<gq, 256, GSM_BYTES>>>(xh, Wqh, Wkh, Wvh, bq, bk, bv,
                                   nullptr, Qh, Kh, Vh, 1);

    dim3 agrid(SEQ / 128, BH);
    attn_h<<<agrid, 256, AT_SMEM_BYTES>>>(Qh, Kh, Vh, Ch);

    dim3 go(DMODEL / TBN, MROWS / TBM, 1);  // (16, 32)
    gemm_h<<<go, 256, GSM_BYTES>>>(Ch, Woh, nullptr, nullptr, bo, nullptr, nullptr,
                                   out, nullptr, nullptr, nullptr, 0);
}